// round 7
// baseline (speedup 1.0000x reference)
#include <cuda_runtime.h>
#include <cuda_bf16.h>
#include <math.h>
#include <stdint.h>

#define HIDDEN  1024
#define NH      16
#define HD      64
#define SEQ     2048
#define BATCH   2
#define BTOK    (BATCH * SEQ)      // 4096
#define QKVCOLS (3 * HIDDEN)       // 3072
#define NBH     (BATCH * NH)       // 32

// ---------------------------------------------------------------------------
// Device-global scratch
// ---------------------------------------------------------------------------
__device__ float g_qkv[(size_t)BTOK * QKVCOLS];

__device__ __nv_bfloat16 g_x_hi[(size_t)BTOK * HIDDEN];
__device__ __nv_bfloat16 g_x_lo[(size_t)BTOK * HIDDEN];
__device__ __nv_bfloat16 g_wq_hi[(size_t)QKVCOLS * HIDDEN];
__device__ __nv_bfloat16 g_wq_lo[(size_t)QKVCOLS * HIDDEN];
__device__ __nv_bfloat16 g_wd_hi[(size_t)HIDDEN * HIDDEN];
__device__ __nv_bfloat16 g_wd_lo[(size_t)HIDDEN * HIDDEN];
__device__ __nv_bfloat16 g_ctx_hi[(size_t)BTOK * HIDDEN];
__device__ __nv_bfloat16 g_ctx_lo[(size_t)BTOK * HIDDEN];

// per-head layouts for attention
__device__ __nv_bfloat16 g_q_hi[(size_t)NBH * SEQ * HD];
__device__ __nv_bfloat16 g_q_lo[(size_t)NBH * SEQ * HD];
__device__ __nv_bfloat16 g_k_hi[(size_t)NBH * SEQ * HD];
__device__ __nv_bfloat16 g_k_lo[(size_t)NBH * SEQ * HD];
__device__ __nv_bfloat16 g_vt_hi[(size_t)NBH * HD * SEQ];   // [bh][d][s]
__device__ __nv_bfloat16 g_vt_lo[(size_t)NBH * HD * SEQ];

// ---------------------------------------------------------------------------
// PTX wrappers (sm_80-class, legal on compute_103)
// ---------------------------------------------------------------------------
__device__ __forceinline__ uint32_t smem_u32(const void* p) {
    uint32_t a;
    asm("{ .reg .u64 t; cvta.to.shared.u64 t, %1; cvt.u32.u64 %0, t; }"
        : "=r"(a) : "l"(p));
    return a;
}

__device__ __forceinline__ void ldm_x4(uint32_t* r, uint32_t addr) {
    asm volatile("ldmatrix.sync.aligned.m8n8.x4.shared.b16 {%0,%1,%2,%3}, [%4];"
                 : "=r"(r[0]), "=r"(r[1]), "=r"(r[2]), "=r"(r[3]) : "r"(addr));
}

__device__ __forceinline__ void mma16816(float* d, const uint32_t* a,
                                         uint32_t b0, uint32_t b1) {
    asm volatile(
        "mma.sync.aligned.m16n8k16.row.col.f32.bf16.bf16.f32 "
        "{%0,%1,%2,%3}, {%4,%5,%6,%7}, {%8,%9}, {%0,%1,%2,%3};"
        : "+f"(d[0]), "+f"(d[1]), "+f"(d[2]), "+f"(d[3])
        : "r"(a[0]), "r"(a[1]), "r"(a[2]), "r"(a[3]), "r"(b0), "r"(b1));
}

__device__ __forceinline__ void cp_async16(uint32_t dst, const void* src) {
    asm volatile("cp.async.cg.shared.global [%0], [%1], 16;"
                 :: "r"(dst), "l"(src));
}
#define CP_COMMIT() asm volatile("cp.async.commit_group;")
#define CP_WAIT(N)  asm volatile("cp.async.wait_group %0;" :: "n"(N))

__device__ __forceinline__ uint32_t pack_hi(float x, float y) {
    __nv_bfloat162 h = __floats2bfloat162_rn(x, y);
    return *(uint32_t*)&h;
}
__device__ __forceinline__ uint32_t pack_lo(float x, float y, uint32_t hi) {
    __nv_bfloat162 h = *(__nv_bfloat162*)&hi;
    __nv_bfloat162 l = __floats2bfloat162_rn(x - __bfloat162float(h.x),
                                             y - __bfloat162float(h.y));
    return *(uint32_t*)&l;
}

// ---------------------------------------------------------------------------
// fp32 -> (bf16 hi, bf16 lo)
// ---------------------------------------------------------------------------
__global__ void cvt_hilo(const float* __restrict__ in,
                         __nv_bfloat16* __restrict__ hi,
                         __nv_bfloat16* __restrict__ lo, int n4)
{
    int i = blockIdx.x * blockDim.x + threadIdx.x;
    if (i >= n4) return;
    float4 v = *(const float4*)&in[i * 4];
    uint32_t h01 = pack_hi(v.x, v.y), h23 = pack_hi(v.z, v.w);
    uint32_t l01 = pack_lo(v.x, v.y, h01), l23 = pack_lo(v.z, v.w, h23);
    *(uint2*)&hi[i * 4] = make_uint2(h01, h23);
    *(uint2*)&lo[i * 4] = make_uint2(l01, l23);
}

// ---------------------------------------------------------------------------
// Split g_qkv (fp32) into per-head Q,K (row-major) and V^T (d-major) hi/lo bf16
// grid (SEQ/64, NBH), block 256
// ---------------------------------------------------------------------------
__global__ void qkv_split(const float* __restrict__ qkv,
                          __nv_bfloat16* __restrict__ qh, __nv_bfloat16* __restrict__ ql,
                          __nv_bfloat16* __restrict__ kh, __nv_bfloat16* __restrict__ kl,
                          __nv_bfloat16* __restrict__ vth, __nv_bfloat16* __restrict__ vtl)
{
    __shared__ uint16_t sh[64][72];
    __shared__ uint16_t sl[64][72];
    const int tid = threadIdx.x;
    const int s0 = blockIdx.x * 64;
    const int bh = blockIdx.y;
    const int b = bh >> 4, h = bh & 15;
    const size_t srow = (size_t)b * SEQ + s0;
    const size_t drow = (size_t)bh * SEQ + s0;

#pragma unroll
    for (int i = 0; i < 4; i++) {
        int id = tid + i * 256;           // 0..1023
        int r = id >> 4;
        int c = (id & 15) << 2;
        const float* src = &qkv[(srow + r) * QKVCOLS + h * HD + c];
        // Q
        {
            float4 v = *(const float4*)src;
            uint32_t h01 = pack_hi(v.x, v.y), h23 = pack_hi(v.z, v.w);
            uint32_t l01 = pack_lo(v.x, v.y, h01), l23 = pack_lo(v.z, v.w, h23);
            *(uint2*)&qh[(drow + r) * HD + c] = make_uint2(h01, h23);
            *(uint2*)&ql[(drow + r) * HD + c] = make_uint2(l01, l23);
        }
        // K
        {
            float4 v = *(const float4*)(src + HIDDEN);
            uint32_t h01 = pack_hi(v.x, v.y), h23 = pack_hi(v.z, v.w);
            uint32_t l01 = pack_lo(v.x, v.y, h01), l23 = pack_lo(v.z, v.w, h23);
            *(uint2*)&kh[(drow + r) * HD + c] = make_uint2(h01, h23);
            *(uint2*)&kl[(drow + r) * HD + c] = make_uint2(l01, l23);
        }
        // V -> transposed staging in smem
        {
            float4 v = *(const float4*)(src + 2 * HIDDEN);
            float vv[4] = {v.x, v.y, v.z, v.w};
#pragma unroll
            for (int t = 0; t < 4; t++) {
                __nv_bfloat16 hb = __float2bfloat16_rn(vv[t]);
                __nv_bfloat16 lb = __float2bfloat16_rn(vv[t] - __bfloat162float(hb));
                sh[c + t][r] = *(uint16_t*)&hb;
                sl[c + t][r] = *(uint16_t*)&lb;
            }
        }
    }
    __syncthreads();

    const size_t vbase = (size_t)bh * HD * SEQ + s0;
#pragma unroll
    for (int i = 0; i < 2; i++) {
        int id = tid + i * 256;           // 0..511
        int d = id >> 3;
        int c8 = (id & 7) << 3;
        *(uint4*)&vth[vbase + (size_t)d * SEQ + c8] = *(uint4*)&sh[d][c8];
        *(uint4*)&vtl[vbase + (size_t)d * SEQ + c8] = *(uint4*)&sl[d][c8];
    }
}

// ===========================================================================
// bf16 split-precision GEMM (BK=32, double-buffered -> 80KB smem -> 2 CTA/SM)
// C[M,N] = A[M,K] @ B[N,K]^T, tile 128x128, 8 warps (2m x 4n, warp 64x32)
// ===========================================================================
#define STRD 40
#define ATILE_B (128 * STRD * 2)      // 10240
#define GBUF_B  (4 * ATILE_B)         // 40960
#define GSMEM_B (2 * GBUF_B)          // 81920

__global__ __launch_bounds__(256, 2)
void gemm_bf16(const __nv_bfloat16* __restrict__ Ahi,
               const __nv_bfloat16* __restrict__ Alo,
               const __nv_bfloat16* __restrict__ Bhi,
               const __nv_bfloat16* __restrict__ Blo,
               float* __restrict__ C, int N, int K)
{
    extern __shared__ char sm[];
    const uint32_t smb = smem_u32(sm);
    const int tid = threadIdx.x;
    const int wid = tid >> 5;
    const int lane = tid & 31;
    const int wm = wid & 1;
    const int wn = wid >> 1;
    const int n0 = blockIdx.x * 128;
    const int m0 = blockIdx.y * 128;

    const int cr = tid >> 1;                  // row 0..127
    const int cc = (tid & 1) << 4;            // element col 0 or 16
    const size_t gA = (size_t)(m0 + cr) * K + cc;
    const size_t gB = (size_t)(n0 + cr) * K + cc;
    const uint32_t sRow = (uint32_t)(cr * STRD + cc) * 2;

    float acc[4][4][4];
#pragma unroll
    for (int i = 0; i < 4; i++)
#pragma unroll
        for (int j = 0; j < 4; j++)
#pragma unroll
            for (int f = 0; f < 4; f++) acc[i][j][f] = 0.f;

    const uint32_t aoff = ((wm * 64 + (lane & 15)) * STRD + ((lane >> 4) << 3)) * 2;
    const uint32_t boff = ((wn * 32 + (lane & 15)) * STRD + ((lane >> 4) << 3)) * 2;

    const int nch = K >> 5;

    auto issue = [&](int buf, int k0) {
        uint32_t base = smb + buf * GBUF_B;
#pragma unroll
        for (int q = 0; q < 2; q++) {
            uint32_t so = sRow + q * 16;
            int go = k0 + q * 8;
            cp_async16(base + 0 * ATILE_B + so, Ahi + gA + go);
            cp_async16(base + 1 * ATILE_B + so, Alo + gA + go);
            cp_async16(base + 2 * ATILE_B + so, Bhi + gB + go);
            cp_async16(base + 3 * ATILE_B + so, Blo + gB + go);
        }
        CP_COMMIT();
    };

    issue(0, 0);

    for (int ch = 0; ch < nch; ch++) {
        const int buf = ch & 1;
        if (ch + 1 < nch) { issue(1 - buf, (ch + 1) << 5); CP_WAIT(1); }
        else              { CP_WAIT(0); }
        __syncthreads();

        const uint32_t tAhi = smb + buf * GBUF_B;
        const uint32_t tAlo = tAhi + ATILE_B;
        const uint32_t tBhi = tAhi + 2 * ATILE_B;
        const uint32_t tBlo = tAhi + 3 * ATILE_B;

#pragma unroll
        for (int kk = 0; kk < 2; kk++) {
            const uint32_t ko = kk * 32;
            uint32_t ah[4][4], bh[2][4];
#pragma unroll
            for (int mi = 0; mi < 4; mi++)
                ldm_x4(ah[mi], tAhi + aoff + mi * (16 * STRD * 2) + ko);
#pragma unroll
            for (int nt = 0; nt < 2; nt++)
                ldm_x4(bh[nt], tBhi + boff + nt * (16 * STRD * 2) + ko);
#pragma unroll
            for (int mi = 0; mi < 4; mi++)
#pragma unroll
                for (int nt = 0; nt < 2; nt++)
#pragma unroll
                    for (int h = 0; h < 2; h++)
                        mma16816(acc[mi][nt * 2 + h], ah[mi], bh[nt][h], bh[nt][h + 2]);
            {
                uint32_t bl[2][4];
#pragma unroll
                for (int nt = 0; nt < 2; nt++)
                    ldm_x4(bl[nt], tBlo + boff + nt * (16 * STRD * 2) + ko);
#pragma unroll
                for (int mi = 0; mi < 4; mi++)
#pragma unroll
                    for (int nt = 0; nt < 2; nt++)
#pragma unroll
                        for (int h = 0; h < 2; h++)
                            mma16816(acc[mi][nt * 2 + h], ah[mi], bl[nt][h], bl[nt][h + 2]);
            }
            {
                uint32_t al[4][4];
#pragma unroll
                for (int mi = 0; mi < 4; mi++)
                    ldm_x4(al[mi], tAlo + aoff + mi * (16 * STRD * 2) + ko);
#pragma unroll
                for (int mi = 0; mi < 4; mi++)
#pragma unroll
                    for (int nt = 0; nt < 2; nt++)
#pragma unroll
                        for (int h = 0; h < 2; h++)
                            mma16816(acc[mi][nt * 2 + h], al[mi], bh[nt][h], bh[nt][h + 2]);
            }
        }
        __syncthreads();
    }

    const int mrow = m0 + wm * 64 + (lane >> 2);
    const int ncol = n0 + wn * 32 + (lane & 3) * 2;
#pragma unroll
    for (int mi = 0; mi < 4; mi++)
#pragma unroll
        for (int nj = 0; nj < 4; nj++) {
            float* d = acc[mi][nj];
            size_t r0 = (size_t)(mrow + mi * 16) * N + ncol + nj * 8;
            size_t r1 = r0 + 8 * (size_t)N;
            *(float2*)&C[r0] = make_float2(d[0], d[1]);
            *(float2*)&C[r1] = make_float2(d[2], d[3]);
        }
}

// ===========================================================================
// Tensor-core flash attention (bf16 split, fp32 softmax)
// grid (SEQ/128, NBH), 256 threads = 8 warps, warp tile m16 x all 64 kv/hd
// ===========================================================================
#define KSTRD 72
#define KTILE_B (64 * KSTRD * 2)     // 9216
#define ABUF_B  (4 * KTILE_B)        // 36864
#define ATT_SMEM (2 * ABUF_B)        // 73728

__global__ __launch_bounds__(256, 2)
void attn_tc(const __nv_bfloat16* __restrict__ Qh, const __nv_bfloat16* __restrict__ Ql,
             const __nv_bfloat16* __restrict__ Kh, const __nv_bfloat16* __restrict__ Kl,
             const __nv_bfloat16* __restrict__ Vth, const __nv_bfloat16* __restrict__ Vtl,
             __nv_bfloat16* __restrict__ ctx_hi, __nv_bfloat16* __restrict__ ctx_lo)
{
    extern __shared__ char sm[];
    const uint32_t smb = smem_u32(sm);
    const int tid = threadIdx.x;
    const int wid = tid >> 5;
    const int lane = tid & 31;
    const int q0 = blockIdx.x * 128;
    const int bh = blockIdx.y;
    const size_t qbase = ((size_t)bh * SEQ + q0) * HD;
    const size_t kbase = (size_t)bh * SEQ * HD;
    const size_t vbase = (size_t)bh * HD * SEQ;

    // ---- Stage Q tile (128x64 hi/lo) into smem, load A fragments ----
#pragma unroll
    for (int p = 0; p < 4; p++) {
        int id = tid + p * 256;               // 0..1023
        int r = id >> 3;
        int c = (id & 7) << 3;
        uint32_t so = (uint32_t)(r * KSTRD + c) * 2;
        cp_async16(smb + so, Qh + qbase + r * HD + c);
        cp_async16(smb + (128 * KSTRD * 2) + so, Ql + qbase + r * HD + c);
    }
    CP_COMMIT(); CP_WAIT(0);
    __syncthreads();

    uint32_t qhf[4][4], qlf[4][4];
    const uint32_t qoff = ((wid * 16 + (lane & 15)) * KSTRD + ((lane >> 4) << 3)) * 2;
#pragma unroll
    for (int ks = 0; ks < 4; ks++) {
        ldm_x4(qhf[ks], smb + qoff + ks * 32);
        ldm_x4(qlf[ks], smb + (128 * KSTRD * 2) + qoff + ks * 32);
    }
    __syncthreads();   // smem now free for KV double buffer

    // ---- KV streaming ----
    auto kv_issue = [&](int buf, int kv0) {
        uint32_t base = smb + buf * ABUF_B;
#pragma unroll
        for (int p = 0; p < 2; p++) {
            int id = tid + p * 256;           // 0..511
            int r = id >> 3;
            int c = (id & 7) << 3;
            uint32_t so = (uint32_t)(r * KSTRD + c) * 2;
            size_t kg = kbase + (size_t)(kv0 + r) * HD + c;
            cp_async16(base + 0 * KTILE_B + so, Kh + kg);
            cp_async16(base + 1 * KTILE_B + so, Kl + kg);
            size_t vg = vbase + (size_t)r * SEQ + kv0 + c;
            cp_async16(base + 2 * KTILE_B + so, Vth + vg);
            cp_async16(base + 3 * KTILE_B + so, Vtl + vg);
        }
        CP_COMMIT();
    };

    float oacc[8][4];
#pragma unroll
    for (int j = 0; j < 8; j++)
#pragma unroll
        for (int f = 0; f < 4; f++) oacc[j][f] = 0.f;
    float mrow0 = -1e30f, mrow1 = -1e30f, lrow0 = 0.f, lrow1 = 0.f;

    const uint32_t frow = ((lane & 15) * KSTRD + ((lane >> 4) << 3)) * 2;
    const float scale = 0.125f;

    kv_issue(0, 0);

    for (int ch = 0; ch < SEQ / 64; ch++) {
        const int buf = ch & 1;
        if (ch + 1 < SEQ / 64) { kv_issue(1 - buf, (ch + 1) * 64); CP_WAIT(1); }
        else                   { CP_WAIT(0); }
        __syncthreads();

        const uint32_t tKh = smb + buf * ABUF_B;
        const uint32_t tKl = tKh + KTILE_B;
        const uint32_t tVh = tKh + 2 * KTILE_B;
        const uint32_t tVl = tKh + 3 * KTILE_B;

        // ---- S = Q @ K^T (3-term split) ----
        float s[8][4];
#pragma unroll
        for (int j = 0; j < 8; j++)
#pragma unroll
            for (int f = 0; f < 4; f++) s[j][f] = 0.f;

#pragma unroll
        for (int ks = 0; ks < 4; ks++) {
            const uint32_t ko = ks * 32;
#pragma unroll
            for (int g = 0; g < 4; g++) {
                uint32_t bf[4];
                ldm_x4(bf, tKh + frow + g * (16 * KSTRD * 2) + ko);
#pragma unroll
                for (int h = 0; h < 2; h++) {
                    mma16816(s[2 * g + h], qhf[ks], bf[h], bf[h + 2]);
                    mma16816(s[2 * g + h], qlf[ks], bf[h], bf[h + 2]);
                }
            }
#pragma unroll
            for (int g = 0; g < 4; g++) {
                uint32_t bf[4];
                ldm_x4(bf, tKl + frow + g * (16 * KSTRD * 2) + ko);
#pragma unroll
                for (int h = 0; h < 2; h++)
                    mma16816(s[2 * g + h], qhf[ks], bf[h], bf[h + 2]);
            }
        }

        // ---- online softmax (rows: r=lane>>2 and r+8) ----
        float rm0 = -1e30f, rm1 = -1e30f;
#pragma unroll
        for (int j = 0; j < 8; j++) {
            s[j][0] *= scale; s[j][1] *= scale; s[j][2] *= scale; s[j][3] *= scale;
            rm0 = fmaxf(rm0, fmaxf(s[j][0], s[j][1]));
            rm1 = fmaxf(rm1, fmaxf(s[j][2], s[j][3]));
        }
#pragma unroll
        for (int off = 1; off <= 2; off <<= 1) {
            rm0 = fmaxf(rm0, __shfl_xor_sync(0xffffffffu, rm0, off));
            rm1 = fmaxf(rm1, __shfl_xor_sync(0xffffffffu, rm1, off));
        }
        float mn0 = fmaxf(mrow0, rm0), mn1 = fmaxf(mrow1, rm1);
        float a0 = __expf(mrow0 - mn0), a1 = __expf(mrow1 - mn1);
        mrow0 = mn0; mrow1 = mn1;
        float rs0 = 0.f, rs1 = 0.f;
#pragma unroll
        for (int j = 0; j < 8; j++) {
            s[j][0] = __expf(s[j][0] - mn0); rs0 += s[j][0];
            s[j][1] = __expf(s[j][1] - mn0); rs0 += s[j][1];
            s[j][2] = __expf(s[j][2] - mn1); rs1 += s[j][2];
            s[j][3] = __expf(s[j][3] - mn1); rs1 += s[j][3];
        }
#pragma unroll
        for (int off = 1; off <= 2; off <<= 1) {
            rs0 += __shfl_xor_sync(0xffffffffu, rs0, off);
            rs1 += __shfl_xor_sync(0xffffffffu, rs1, off);
        }
        lrow0 = lrow0 * a0 + rs0;
        lrow1 = lrow1 * a1 + rs1;
#pragma unroll
        for (int j = 0; j < 8; j++) {
            oacc[j][0] *= a0; oacc[j][1] *= a0;
            oacc[j][2] *= a1; oacc[j][3] *= a1;
        }

        // ---- O += P @ V (3-term split, P in registers) ----
#pragma unroll
        for (int kc = 0; kc < 4; kc++) {
            uint32_t pa_h[4], pa_l[4];
            pa_h[0] = pack_hi(s[2 * kc][0], s[2 * kc][1]);
            pa_l[0] = pack_lo(s[2 * kc][0], s[2 * kc][1], pa_h[0]);
            pa_h[1] = pack_hi(s[2 * kc][2], s[2 * kc][3]);
            pa_l[1] = pack_lo(s[2 * kc][2], s[2 * kc][3], pa_h[1]);
            pa_h[2] = pack_hi(s[2 * kc + 1][0], s[2 * kc + 1][1]);
            pa_l[2] = pack_lo(s[2 * kc + 1][0], s[2 * kc + 1][1], pa_h[2]);
            pa_h[3] = pack_hi(s[2 * kc + 1][2], s[2 * kc + 1][3]);
            pa_l[3] = pack_lo(s[2 * kc + 1][2], s[2 * kc + 1][3], pa_h[3]);

            const uint32_t ko = kc * 32;
#pragma unroll
            for (int g = 0; g < 4; g++) {
                uint32_t vf[4];
                ldm_x4(vf, tVh + frow + g * (16 * KSTRD * 2) + ko);
#pragma unroll
                for (int h = 0; h < 2; h++) {
                    mma16816(oacc[2 * g + h], pa_h, vf[h], vf[h + 2]);
                    mma16816(oacc[2 * g + h], pa_l, vf[h], vf[h + 2]);
                }
            }
#pragma unroll
            for (int g = 0; g < 4; g++) {
                uint32_t vf[4];
                ldm_x4(vf, tVl + frow + g * (16 * KSTRD * 2) + ko);
#pragma unroll
                for (int h = 0; h < 2; h++)
                    mma16816(oacc[2 * g + h], pa_h, vf[h], vf[h + 2]);
            }
        }
        __syncthreads();   // everyone done with buf before it is refilled
    }

    // ---- epilogue: ctx hi/lo bf16 ----
    const int b = bh >> 4, h = bh & 15;
    const float inv0 = 1.f / lrow0, inv1 = 1.f / lrow1;
    const size_t row0 = (size_t)b * SEQ + q0 + wid * 16 + (lane >> 2);
    const size_t row1 = row0 + 8;
#pragma unroll
    for (int j = 0; j < 8; j++) {
        int col = h * HD + j * 8 + 2 * (lane & 3);
        float v0 = oacc[j][0] * inv0, v1 = oacc[j][1] * inv0;
        float v2 = oacc[j][2] * inv1, v3 = oacc[j][3] * inv1;
        uint32_t h01 = pack_hi(v0, v1), h23 = pack_hi(v2, v3);
        uint32_t l01 = pack_lo(v0, v1, h01), l23 = pack_lo(v2, v3, h23);
        *(uint32_t*)&ctx_hi[row0 * HIDDEN + col] = h01;
        *(uint32_t*)&ctx_lo[row0 * HIDDEN + col] = l01;
        *(uint32_t*)&ctx_hi[row1 * HIDDEN + col] = h23;
        *(uint32_t*)&ctx_lo[row1 * HIDDEN + col] = l23;
    }
}

// ---------------------------------------------------------------------------
extern "C" void kernel_launch(void* const* d_in, const int* in_sizes, int n_in,
                              void* d_out, int out_size)
{
    const float* x       = (const float*)d_in[0];
    const float* w_qkv   = (const float*)d_in[1];
    const float* w_dense = (const float*)d_in[2];
    float* out           = (float*)d_out;

    float* qkv;
    __nv_bfloat16 *xh, *xl, *wqh, *wql, *wdh, *wdl, *ch, *cl;
    __nv_bfloat16 *q_h, *q_l, *k_h, *k_l, *vt_h, *vt_l;
    cudaGetSymbolAddress((void**)&qkv, g_qkv);
    cudaGetSymbolAddress((void**)&xh, g_x_hi);   cudaGetSymbolAddress((void**)&xl, g_x_lo);
    cudaGetSymbolAddress((void**)&wqh, g_wq_hi); cudaGetSymbolAddress((void**)&wql, g_wq_lo);
    cudaGetSymbolAddress((void**)&wdh, g_wd_hi); cudaGetSymbolAddress((void**)&wdl, g_wd_lo);
    cudaGetSymbolAddress((void**)&ch, g_ctx_hi); cudaGetSymbolAddress((void**)&cl, g_ctx_lo);
    cudaGetSymbolAddress((void**)&q_h, g_q_hi);  cudaGetSymbolAddress((void**)&q_l, g_q_lo);
    cudaGetSymbolAddress((void**)&k_h, g_k_hi);  cudaGetSymbolAddress((void**)&k_l, g_k_lo);
    cudaGetSymbolAddress((void**)&vt_h, g_vt_hi); cudaGetSymbolAddress((void**)&vt_l, g_vt_lo);

    cudaFuncSetAttribute(gemm_bf16, cudaFuncAttributeMaxDynamicSharedMemorySize, GSMEM_B);
    cudaFuncSetAttribute(attn_tc, cudaFuncAttributeMaxDynamicSharedMemorySize, ATT_SMEM);

    // 0) operand conversions
    {
        int n4 = BTOK * HIDDEN / 4;
        cvt_hilo<<<(n4 + 255) / 256, 256>>>(x, xh, xl, n4);
        n4 = QKVCOLS * HIDDEN / 4;
        cvt_hilo<<<(n4 + 255) / 256, 256>>>(w_qkv, wqh, wql, n4);
        n4 = HIDDEN * HIDDEN / 4;
        cvt_hilo<<<(n4 + 255) / 256, 256>>>(w_dense, wdh, wdl, n4);
    }

    // 1) QKV projection (tensor cores)
    {
        dim3 grid(QKVCOLS / 128, BTOK / 128);
        gemm_bf16<<<grid, 256, GSMEM_B>>>(xh, xl, wqh, wql, qkv, QKVCOLS, HIDDEN);
    }

    // 2) split into per-head bf16 hi/lo Q, K, V^T
    {
        dim3 grid(SEQ / 64, NBH);
        qkv_split<<<grid, 256>>>(qkv, q_h, q_l, k_h, k_l, vt_h, vt_l);
    }

    // 3) attention (tensor cores) -> ctx hi/lo
    {
        dim3 grid(SEQ / 128, NBH);
        attn_tc<<<grid, 256, ATT_SMEM>>>(q_h, q_l, k_h, k_l, vt_h, vt_l, ch, cl);
    }

    // 4) output dense (tensor cores)
    {
        dim3 grid(HIDDEN / 128, BTOK / 128);
        gemm_bf16<<<grid, 256, GSMEM_B>>>(ch, cl, wdh, wdl, out, HIDDEN, HIDDEN);
    }
}

// round 9
// speedup vs baseline: 1.0027x; 1.0027x over previous
#include <cuda_runtime.h>
#include <cuda_bf16.h>
#include <math.h>
#include <stdint.h>

#define HIDDEN  1024
#define NH      16
#define HD      64
#define SEQ     2048
#define BATCH   2
#define BTOK    (BATCH * SEQ)      // 4096
#define QKVCOLS (3 * HIDDEN)       // 3072
#define NBH     (BATCH * NH)       // 32

// ---------------------------------------------------------------------------
// Device-global scratch
// ---------------------------------------------------------------------------
__device__ float g_qkv[(size_t)BTOK * QKVCOLS];

__device__ __nv_bfloat16 g_x_hi[(size_t)BTOK * HIDDEN];
__device__ __nv_bfloat16 g_x_lo[(size_t)BTOK * HIDDEN];
__device__ __nv_bfloat16 g_wq_hi[(size_t)QKVCOLS * HIDDEN];
__device__ __nv_bfloat16 g_wq_lo[(size_t)QKVCOLS * HIDDEN];
__device__ __nv_bfloat16 g_wd_hi[(size_t)HIDDEN * HIDDEN];
__device__ __nv_bfloat16 g_wd_lo[(size_t)HIDDEN * HIDDEN];
__device__ __nv_bfloat16 g_ctx_hi[(size_t)BTOK * HIDDEN];
__device__ __nv_bfloat16 g_ctx_lo[(size_t)BTOK * HIDDEN];

// per-head layouts for attention
__device__ __nv_bfloat16 g_q_hi[(size_t)NBH * SEQ * HD];
__device__ __nv_bfloat16 g_q_lo[(size_t)NBH * SEQ * HD];
__device__ __nv_bfloat16 g_k_hi[(size_t)NBH * SEQ * HD];
__device__ __nv_bfloat16 g_k_lo[(size_t)NBH * SEQ * HD];
__device__ __nv_bfloat16 g_vt_hi[(size_t)NBH * HD * SEQ];   // [bh][d][s]
__device__ __nv_bfloat16 g_vt_lo[(size_t)NBH * HD * SEQ];

// ---------------------------------------------------------------------------
// PTX wrappers (sm_80-class, legal on compute_103)
// ---------------------------------------------------------------------------
__device__ __forceinline__ uint32_t smem_u32(const void* p) {
    uint32_t a;
    asm("{ .reg .u64 t; cvta.to.shared.u64 t, %1; cvt.u32.u64 %0, t; }"
        : "=r"(a) : "l"(p));
    return a;
}

__device__ __forceinline__ void ldm_x4(uint32_t* r, uint32_t addr) {
    asm volatile("ldmatrix.sync.aligned.m8n8.x4.shared.b16 {%0,%1,%2,%3}, [%4];"
                 : "=r"(r[0]), "=r"(r[1]), "=r"(r[2]), "=r"(r[3]) : "r"(addr));
}

__device__ __forceinline__ void mma16816(float* d, const uint32_t* a,
                                         uint32_t b0, uint32_t b1) {
    asm volatile(
        "mma.sync.aligned.m16n8k16.row.col.f32.bf16.bf16.f32 "
        "{%0,%1,%2,%3}, {%4,%5,%6,%7}, {%8,%9}, {%0,%1,%2,%3};"
        : "+f"(d[0]), "+f"(d[1]), "+f"(d[2]), "+f"(d[3])
        : "r"(a[0]), "r"(a[1]), "r"(a[2]), "r"(a[3]), "r"(b0), "r"(b1));
}

__device__ __forceinline__ void cp_async16(uint32_t dst, const void* src) {
    asm volatile("cp.async.cg.shared.global [%0], [%1], 16;"
                 :: "r"(dst), "l"(src));
}
#define CP_COMMIT() asm volatile("cp.async.commit_group;")
#define CP_WAIT(N)  asm volatile("cp.async.wait_group %0;" :: "n"(N))

__device__ __forceinline__ uint32_t pack_hi(float x, float y) {
    __nv_bfloat162 h = __floats2bfloat162_rn(x, y);
    return *(uint32_t*)&h;
}
__device__ __forceinline__ uint32_t pack_lo(float x, float y, uint32_t hi) {
    __nv_bfloat162 h = *(__nv_bfloat162*)&hi;
    __nv_bfloat162 l = __floats2bfloat162_rn(x - __bfloat162float(h.x),
                                             y - __bfloat162float(h.y));
    return *(uint32_t*)&l;
}

// ---------------------------------------------------------------------------
// fp32 -> (bf16 hi, bf16 lo)
// ---------------------------------------------------------------------------
__global__ void cvt_hilo(const float* __restrict__ in,
                         __nv_bfloat16* __restrict__ hi,
                         __nv_bfloat16* __restrict__ lo, int n4)
{
    int i = blockIdx.x * blockDim.x + threadIdx.x;
    if (i >= n4) return;
    float4 v = *(const float4*)&in[i * 4];
    uint32_t h01 = pack_hi(v.x, v.y), h23 = pack_hi(v.z, v.w);
    uint32_t l01 = pack_lo(v.x, v.y, h01), l23 = pack_lo(v.z, v.w, h23);
    *(uint2*)&hi[i * 4] = make_uint2(h01, h23);
    *(uint2*)&lo[i * 4] = make_uint2(l01, l23);
}

// ---------------------------------------------------------------------------
// Split g_qkv (fp32) into per-head Q,K (row-major) and V^T (d-major) hi/lo bf16
// grid (SEQ/64, NBH), block 256
// ---------------------------------------------------------------------------
__global__ void qkv_split(const float* __restrict__ qkv,
                          __nv_bfloat16* __restrict__ qh, __nv_bfloat16* __restrict__ ql,
                          __nv_bfloat16* __restrict__ kh, __nv_bfloat16* __restrict__ kl,
                          __nv_bfloat16* __restrict__ vth, __nv_bfloat16* __restrict__ vtl)
{
    __shared__ uint16_t sh[64][72];
    __shared__ uint16_t sl[64][72];
    const int tid = threadIdx.x;
    const int s0 = blockIdx.x * 64;
    const int bh = blockIdx.y;
    const int b = bh >> 4, h = bh & 15;
    const size_t srow = (size_t)b * SEQ + s0;
    const size_t drow = (size_t)bh * SEQ + s0;

#pragma unroll
    for (int i = 0; i < 4; i++) {
        int id = tid + i * 256;           // 0..1023
        int r = id >> 4;
        int c = (id & 15) << 2;
        const float* src = &qkv[(srow + r) * QKVCOLS + h * HD + c];
        // Q
        {
            float4 v = *(const float4*)src;
            uint32_t h01 = pack_hi(v.x, v.y), h23 = pack_hi(v.z, v.w);
            uint32_t l01 = pack_lo(v.x, v.y, h01), l23 = pack_lo(v.z, v.w, h23);
            *(uint2*)&qh[(drow + r) * HD + c] = make_uint2(h01, h23);
            *(uint2*)&ql[(drow + r) * HD + c] = make_uint2(l01, l23);
        }
        // K
        {
            float4 v = *(const float4*)(src + HIDDEN);
            uint32_t h01 = pack_hi(v.x, v.y), h23 = pack_hi(v.z, v.w);
            uint32_t l01 = pack_lo(v.x, v.y, h01), l23 = pack_lo(v.z, v.w, h23);
            *(uint2*)&kh[(drow + r) * HD + c] = make_uint2(h01, h23);
            *(uint2*)&kl[(drow + r) * HD + c] = make_uint2(l01, l23);
        }
        // V -> transposed staging in smem
        {
            float4 v = *(const float4*)(src + 2 * HIDDEN);
            float vv[4] = {v.x, v.y, v.z, v.w};
#pragma unroll
            for (int t = 0; t < 4; t++) {
                __nv_bfloat16 hb = __float2bfloat16_rn(vv[t]);
                __nv_bfloat16 lb = __float2bfloat16_rn(vv[t] - __bfloat162float(hb));
                sh[c + t][r] = *(uint16_t*)&hb;
                sl[c + t][r] = *(uint16_t*)&lb;
            }
        }
    }
    __syncthreads();

    const size_t vbase = (size_t)bh * HD * SEQ + s0;
#pragma unroll
    for (int i = 0; i < 2; i++) {
        int id = tid + i * 256;           // 0..511
        int d = id >> 3;
        int c8 = (id & 7) << 3;
        *(uint4*)&vth[vbase + (size_t)d * SEQ + c8] = *(uint4*)&sh[d][c8];
        *(uint4*)&vtl[vbase + (size_t)d * SEQ + c8] = *(uint4*)&sl[d][c8];
    }
}

// ===========================================================================
// bf16 split-precision GEMM (BK=32, double-buffered -> 80KB smem -> 2 CTA/SM)
// C[M,N] = A[M,K] @ B[N,K]^T, tile 128x128, 8 warps (2m x 4n, warp 64x32)
// ===========================================================================
#define STRD 40
#define ATILE_B (128 * STRD * 2)      // 10240
#define GBUF_B  (4 * ATILE_B)         // 40960
#define GSMEM_B (2 * GBUF_B)          // 81920

__global__ __launch_bounds__(256, 2)
void gemm_bf16(const __nv_bfloat16* __restrict__ Ahi,
               const __nv_bfloat16* __restrict__ Alo,
               const __nv_bfloat16* __restrict__ Bhi,
               const __nv_bfloat16* __restrict__ Blo,
               float* __restrict__ C, int N, int K)
{
    extern __shared__ char sm[];
    const uint32_t smb = smem_u32(sm);
    const int tid = threadIdx.x;
    const int wid = tid >> 5;
    const int lane = tid & 31;
    const int wm = wid & 1;
    const int wn = wid >> 1;
    const int n0 = blockIdx.x * 128;
    const int m0 = blockIdx.y * 128;

    const int cr = tid >> 1;                  // row 0..127
    const int cc = (tid & 1) << 4;            // element col 0 or 16
    const size_t gA = (size_t)(m0 + cr) * K + cc;
    const size_t gB = (size_t)(n0 + cr) * K + cc;
    const uint32_t sRow = (uint32_t)(cr * STRD + cc) * 2;

    float acc[4][4][4];
#pragma unroll
    for (int i = 0; i < 4; i++)
#pragma unroll
        for (int j = 0; j < 4; j++)
#pragma unroll
            for (int f = 0; f < 4; f++) acc[i][j][f] = 0.f;

    const uint32_t aoff = ((wm * 64 + (lane & 15)) * STRD + ((lane >> 4) << 3)) * 2;
    const uint32_t boff = ((wn * 32 + (lane & 15)) * STRD + ((lane >> 4) << 3)) * 2;

    const int nch = K >> 5;

    auto issue = [&](int buf, int k0) {
        uint32_t base = smb + buf * GBUF_B;
#pragma unroll
        for (int q = 0; q < 2; q++) {
            uint32_t so = sRow + q * 16;
            int go = k0 + q * 8;
            cp_async16(base + 0 * ATILE_B + so, Ahi + gA + go);
            cp_async16(base + 1 * ATILE_B + so, Alo + gA + go);
            cp_async16(base + 2 * ATILE_B + so, Bhi + gB + go);
            cp_async16(base + 3 * ATILE_B + so, Blo + gB + go);
        }
        CP_COMMIT();
    };

    issue(0, 0);

    for (int ch = 0; ch < nch; ch++) {
        const int buf = ch & 1;
        if (ch + 1 < nch) { issue(1 - buf, (ch + 1) << 5); CP_WAIT(1); }
        else              { CP_WAIT(0); }
        __syncthreads();

        const uint32_t tAhi = smb + buf * GBUF_B;
        const uint32_t tAlo = tAhi + ATILE_B;
        const uint32_t tBhi = tAhi + 2 * ATILE_B;
        const uint32_t tBlo = tAhi + 3 * ATILE_B;

#pragma unroll
        for (int kk = 0; kk < 2; kk++) {
            const uint32_t ko = kk * 32;
            uint32_t ah[4][4], bh[2][4];
#pragma unroll
            for (int mi = 0; mi < 4; mi++)
                ldm_x4(ah[mi], tAhi + aoff + mi * (16 * STRD * 2) + ko);
#pragma unroll
            for (int nt = 0; nt < 2; nt++)
                ldm_x4(bh[nt], tBhi + boff + nt * (16 * STRD * 2) + ko);
#pragma unroll
            for (int mi = 0; mi < 4; mi++)
#pragma unroll
                for (int nt = 0; nt < 2; nt++)
#pragma unroll
                    for (int h = 0; h < 2; h++)
                        mma16816(acc[mi][nt * 2 + h], ah[mi], bh[nt][h], bh[nt][h + 2]);
            {
                uint32_t bl[2][4];
#pragma unroll
                for (int nt = 0; nt < 2; nt++)
                    ldm_x4(bl[nt], tBlo + boff + nt * (16 * STRD * 2) + ko);
#pragma unroll
                for (int mi = 0; mi < 4; mi++)
#pragma unroll
                    for (int nt = 0; nt < 2; nt++)
#pragma unroll
                        for (int h = 0; h < 2; h++)
                            mma16816(acc[mi][nt * 2 + h], ah[mi], bl[nt][h], bl[nt][h + 2]);
            }
            {
                uint32_t al[4][4];
#pragma unroll
                for (int mi = 0; mi < 4; mi++)
                    ldm_x4(al[mi], tAlo + aoff + mi * (16 * STRD * 2) + ko);
#pragma unroll
                for (int mi = 0; mi < 4; mi++)
#pragma unroll
                    for (int nt = 0; nt < 2; nt++)
#pragma unroll
                        for (int h = 0; h < 2; h++)
                            mma16816(acc[mi][nt * 2 + h], al[mi], bh[nt][h], bh[nt][h + 2]);
            }
        }
        __syncthreads();
    }

    const int mrow = m0 + wm * 64 + (lane >> 2);
    const int ncol = n0 + wn * 32 + (lane & 3) * 2;
#pragma unroll
    for (int mi = 0; mi < 4; mi++)
#pragma unroll
        for (int nj = 0; nj < 4; nj++) {
            float* d = acc[mi][nj];
            size_t r0 = (size_t)(mrow + mi * 16) * N + ncol + nj * 8;
            size_t r1 = r0 + 8 * (size_t)N;
            *(float2*)&C[r0] = make_float2(d[0], d[1]);
            *(float2*)&C[r1] = make_float2(d[2], d[3]);
        }
}

// ===========================================================================
// Tensor-core flash attention (bf16 split, fp32 softmax)
// grid (SEQ/128, NBH), 256 threads = 8 warps, warp tile m16 x all 64 kv/hd
// ===========================================================================
#define KSTRD 72
#define KTILE_B (64 * KSTRD * 2)     // 9216
#define ABUF_B  (4 * KTILE_B)        // 36864
#define ATT_SMEM (2 * ABUF_B)        // 73728

__global__ __launch_bounds__(256, 2)
void attn_tc(const __nv_bfloat16* __restrict__ Qh, const __nv_bfloat16* __restrict__ Ql,
             const __nv_bfloat16* __restrict__ Kh, const __nv_bfloat16* __restrict__ Kl,
             const __nv_bfloat16* __restrict__ Vth, const __nv_bfloat16* __restrict__ Vtl,
             __nv_bfloat16* __restrict__ ctx_hi, __nv_bfloat16* __restrict__ ctx_lo)
{
    extern __shared__ char sm[];
    const uint32_t smb = smem_u32(sm);
    const int tid = threadIdx.x;
    const int wid = tid >> 5;
    const int lane = tid & 31;
    const int q0 = blockIdx.x * 128;
    const int bh = blockIdx.y;
    const size_t qbase = ((size_t)bh * SEQ + q0) * HD;
    const size_t kbase = (size_t)bh * SEQ * HD;
    const size_t vbase = (size_t)bh * HD * SEQ;

    // ---- Stage Q tile (128x64 hi/lo) into smem, load A fragments ----
#pragma unroll
    for (int p = 0; p < 4; p++) {
        int id = tid + p * 256;               // 0..1023
        int r = id >> 3;
        int c = (id & 7) << 3;
        uint32_t so = (uint32_t)(r * KSTRD + c) * 2;
        cp_async16(smb + so, Qh + qbase + r * HD + c);
        cp_async16(smb + (128 * KSTRD * 2) + so, Ql + qbase + r * HD + c);
    }
    CP_COMMIT(); CP_WAIT(0);
    __syncthreads();

    uint32_t qhf[4][4], qlf[4][4];
    const uint32_t qoff = ((wid * 16 + (lane & 15)) * KSTRD + ((lane >> 4) << 3)) * 2;
#pragma unroll
    for (int ks = 0; ks < 4; ks++) {
        ldm_x4(qhf[ks], smb + qoff + ks * 32);
        ldm_x4(qlf[ks], smb + (128 * KSTRD * 2) + qoff + ks * 32);
    }
    __syncthreads();   // smem now free for KV double buffer

    // ---- KV streaming ----
    auto kv_issue = [&](int buf, int kv0) {
        uint32_t base = smb + buf * ABUF_B;
#pragma unroll
        for (int p = 0; p < 2; p++) {
            int id = tid + p * 256;           // 0..511
            int r = id >> 3;
            int c = (id & 7) << 3;
            uint32_t so = (uint32_t)(r * KSTRD + c) * 2;
            size_t kg = kbase + (size_t)(kv0 + r) * HD + c;
            cp_async16(base + 0 * KTILE_B + so, Kh + kg);
            cp_async16(base + 1 * KTILE_B + so, Kl + kg);
            size_t vg = vbase + (size_t)r * SEQ + kv0 + c;
            cp_async16(base + 2 * KTILE_B + so, Vth + vg);
            cp_async16(base + 3 * KTILE_B + so, Vtl + vg);
        }
        CP_COMMIT();
    };

    float oacc[8][4];
#pragma unroll
    for (int j = 0; j < 8; j++)
#pragma unroll
        for (int f = 0; f < 4; f++) oacc[j][f] = 0.f;
    float mrow0 = -1e30f, mrow1 = -1e30f, lrow0 = 0.f, lrow1 = 0.f;

    const uint32_t frow = ((lane & 15) * KSTRD + ((lane >> 4) << 3)) * 2;
    const float scale = 0.125f;

    kv_issue(0, 0);

    for (int ch = 0; ch < SEQ / 64; ch++) {
        const int buf = ch & 1;
        if (ch + 1 < SEQ / 64) { kv_issue(1 - buf, (ch + 1) * 64); CP_WAIT(1); }
        else                   { CP_WAIT(0); }
        __syncthreads();

        const uint32_t tKh = smb + buf * ABUF_B;
        const uint32_t tKl = tKh + KTILE_B;
        const uint32_t tVh = tKh + 2 * KTILE_B;
        const uint32_t tVl = tKh + 3 * KTILE_B;

        // ---- S = Q @ K^T (3-term split) ----
        float s[8][4];
#pragma unroll
        for (int j = 0; j < 8; j++)
#pragma unroll
            for (int f = 0; f < 4; f++) s[j][f] = 0.f;

#pragma unroll
        for (int ks = 0; ks < 4; ks++) {
            const uint32_t ko = ks * 32;
#pragma unroll
            for (int g = 0; g < 4; g++) {
                uint32_t bf[4];
                ldm_x4(bf, tKh + frow + g * (16 * KSTRD * 2) + ko);
#pragma unroll
                for (int h = 0; h < 2; h++) {
                    mma16816(s[2 * g + h], qhf[ks], bf[h], bf[h + 2]);
                    mma16816(s[2 * g + h], qlf[ks], bf[h], bf[h + 2]);
                }
            }
#pragma unroll
            for (int g = 0; g < 4; g++) {
                uint32_t bf[4];
                ldm_x4(bf, tKl + frow + g * (16 * KSTRD * 2) + ko);
#pragma unroll
                for (int h = 0; h < 2; h++)
                    mma16816(s[2 * g + h], qhf[ks], bf[h], bf[h + 2]);
            }
        }

        // ---- online softmax (rows: r=lane>>2 and r+8) ----
        float rm0 = -1e30f, rm1 = -1e30f;
#pragma unroll
        for (int j = 0; j < 8; j++) {
            s[j][0] *= scale; s[j][1] *= scale; s[j][2] *= scale; s[j][3] *= scale;
            rm0 = fmaxf(rm0, fmaxf(s[j][0], s[j][1]));
            rm1 = fmaxf(rm1, fmaxf(s[j][2], s[j][3]));
        }
#pragma unroll
        for (int off = 1; off <= 2; off <<= 1) {
            rm0 = fmaxf(rm0, __shfl_xor_sync(0xffffffffu, rm0, off));
            rm1 = fmaxf(rm1, __shfl_xor_sync(0xffffffffu, rm1, off));
        }
        float mn0 = fmaxf(mrow0, rm0), mn1 = fmaxf(mrow1, rm1);
        float a0 = __expf(mrow0 - mn0), a1 = __expf(mrow1 - mn1);
        mrow0 = mn0; mrow1 = mn1;
        float rs0 = 0.f, rs1 = 0.f;
#pragma unroll
        for (int j = 0; j < 8; j++) {
            s[j][0] = __expf(s[j][0] - mn0); rs0 += s[j][0];
            s[j][1] = __expf(s[j][1] - mn0); rs0 += s[j][1];
            s[j][2] = __expf(s[j][2] - mn1); rs1 += s[j][2];
            s[j][3] = __expf(s[j][3] - mn1); rs1 += s[j][3];
        }
#pragma unroll
        for (int off = 1; off <= 2; off <<= 1) {
            rs0 += __shfl_xor_sync(0xffffffffu, rs0, off);
            rs1 += __shfl_xor_sync(0xffffffffu, rs1, off);
        }
        lrow0 = lrow0 * a0 + rs0;
        lrow1 = lrow1 * a1 + rs1;
#pragma unroll
        for (int j = 0; j < 8; j++) {
            oacc[j][0] *= a0; oacc[j][1] *= a0;
            oacc[j][2] *= a1; oacc[j][3] *= a1;
        }

        // ---- O += P @ V (3-term split, P in registers) ----
#pragma unroll
        for (int kc = 0; kc < 4; kc++) {
            uint32_t pa_h[4], pa_l[4];
            pa_h[0] = pack_hi(s[2 * kc][0], s[2 * kc][1]);
            pa_l[0] = pack_lo(s[2 * kc][0], s[2 * kc][1], pa_h[0]);
            pa_h[1] = pack_hi(s[2 * kc][2], s[2 * kc][3]);
            pa_l[1] = pack_lo(s[2 * kc][2], s[2 * kc][3], pa_h[1]);
            pa_h[2] = pack_hi(s[2 * kc + 1][0], s[2 * kc + 1][1]);
            pa_l[2] = pack_lo(s[2 * kc + 1][0], s[2 * kc + 1][1], pa_h[2]);
            pa_h[3] = pack_hi(s[2 * kc + 1][2], s[2 * kc + 1][3]);
            pa_l[3] = pack_lo(s[2 * kc + 1][2], s[2 * kc + 1][3], pa_h[3]);

            const uint32_t ko = kc * 32;
#pragma unroll
            for (int g = 0; g < 4; g++) {
                uint32_t vf[4];
                ldm_x4(vf, tVh + frow + g * (16 * KSTRD * 2) + ko);
#pragma unroll
                for (int h = 0; h < 2; h++) {
                    mma16816(oacc[2 * g + h], pa_h, vf[h], vf[h + 2]);
                    mma16816(oacc[2 * g + h], pa_l, vf[h], vf[h + 2]);
                }
            }
#pragma unroll
            for (int g = 0; g < 4; g++) {
                uint32_t vf[4];
                ldm_x4(vf, tVl + frow + g * (16 * KSTRD * 2) + ko);
#pragma unroll
                for (int h = 0; h < 2; h++)
                    mma16816(oacc[2 * g + h], pa_h, vf[h], vf[h + 2]);
            }
        }
        __syncthreads();   // everyone done with buf before it is refilled
    }

    // ---- epilogue: ctx hi/lo bf16 ----
    const int b = bh >> 4, h = bh & 15;
    const float inv0 = 1.f / lrow0, inv1 = 1.f / lrow1;
    const size_t row0 = (size_t)b * SEQ + q0 + wid * 16 + (lane >> 2);
    const size_t row1 = row0 + 8;
#pragma unroll
    for (int j = 0; j < 8; j++) {
        int col = h * HD + j * 8 + 2 * (lane & 3);
        float v0 = oacc[j][0] * inv0, v1 = oacc[j][1] * inv0;
        float v2 = oacc[j][2] * inv1, v3 = oacc[j][3] * inv1;
        uint32_t h01 = pack_hi(v0, v1), h23 = pack_hi(v2, v3);
        uint32_t l01 = pack_lo(v0, v1, h01), l23 = pack_lo(v2, v3, h23);
        *(uint32_t*)&ctx_hi[row0 * HIDDEN + col] = h01;
        *(uint32_t*)&ctx_lo[row0 * HIDDEN + col] = l01;
        *(uint32_t*)&ctx_hi[row1 * HIDDEN + col] = h23;
        *(uint32_t*)&ctx_lo[row1 * HIDDEN + col] = l23;
    }
}

// ---------------------------------------------------------------------------
extern "C" void kernel_launch(void* const* d_in, const int* in_sizes, int n_in,
                              void* d_out, int out_size)
{
    const float* x       = (const float*)d_in[0];
    const float* w_qkv   = (const float*)d_in[1];
    const float* w_dense = (const float*)d_in[2];
    float* out           = (float*)d_out;

    float* qkv;
    __nv_bfloat16 *xh, *xl, *wqh, *wql, *wdh, *wdl, *ch, *cl;
    __nv_bfloat16 *q_h, *q_l, *k_h, *k_l, *vt_h, *vt_l;
    cudaGetSymbolAddress((void**)&qkv, g_qkv);
    cudaGetSymbolAddress((void**)&xh, g_x_hi);   cudaGetSymbolAddress((void**)&xl, g_x_lo);
    cudaGetSymbolAddress((void**)&wqh, g_wq_hi); cudaGetSymbolAddress((void**)&wql, g_wq_lo);
    cudaGetSymbolAddress((void**)&wdh, g_wd_hi); cudaGetSymbolAddress((void**)&wdl, g_wd_lo);
    cudaGetSymbolAddress((void**)&ch, g_ctx_hi); cudaGetSymbolAddress((void**)&cl, g_ctx_lo);
    cudaGetSymbolAddress((void**)&q_h, g_q_hi);  cudaGetSymbolAddress((void**)&q_l, g_q_lo);
    cudaGetSymbolAddress((void**)&k_h, g_k_hi);  cudaGetSymbolAddress((void**)&k_l, g_k_lo);
    cudaGetSymbolAddress((void**)&vt_h, g_vt_hi); cudaGetSymbolAddress((void**)&vt_l, g_vt_lo);

    cudaFuncSetAttribute(gemm_bf16, cudaFuncAttributeMaxDynamicSharedMemorySize, GSMEM_B);
    cudaFuncSetAttribute(attn_tc, cudaFuncAttributeMaxDynamicSharedMemorySize, ATT_SMEM);

    // 0) operand conversions
    {
        int n4 = BTOK * HIDDEN / 4;
        cvt_hilo<<<(n4 + 255) / 256, 256>>>(x, xh, xl, n4);
        n4 = QKVCOLS * HIDDEN / 4;
        cvt_hilo<<<(n4 + 255) / 256, 256>>>(w_qkv, wqh, wql, n4);
        n4 = HIDDEN * HIDDEN / 4;
        cvt_hilo<<<(n4 + 255) / 256, 256>>>(w_dense, wdh, wdl, n4);
    }

    // 1) QKV projection (tensor cores)
    {
        dim3 grid(QKVCOLS / 128, BTOK / 128);
        gemm_bf16<<<grid, 256, GSMEM_B>>>(xh, xl, wqh, wql, qkv, QKVCOLS, HIDDEN);
    }

    // 2) split into per-head bf16 hi/lo Q, K, V^T
    {
        dim3 grid(SEQ / 64, NBH);
        qkv_split<<<grid, 256>>>(qkv, q_h, q_l, k_h, k_l, vt_h, vt_l);
    }

    // 3) attention (tensor cores) -> ctx hi/lo
    {
        dim3 grid(SEQ / 128, NBH);
        attn_tc<<<grid, 256, ATT_SMEM>>>(q_h, q_l, k_h, k_l, vt_h, vt_l, ch, cl);
    }

    // 4) output dense (tensor cores)
    {
        dim3 grid(HIDDEN / 128, BTOK / 128);
        gemm_bf16<<<grid, 256, GSMEM_B>>>(ch, cl, wdh, wdl, out, HIDDEN, HIDDEN);
    }
}